// round 3
// baseline (speedup 1.0000x reference)
#include <cuda_runtime.h>
#include <math.h>

// Problem dims (fixed by the dataset)
#define B_ 256
#define S_ 256
#define I_ 3
#define H_ 1024
#define T_ 64
#define BH (B_*H_)

// GEMM tile config: BM x BN output tile, BK k-slice, 128 threads, 4x4 microtile.
// grid for a step GEMM = (H/BN=16, B/BM=8) = 128 blocks -> ~1 block/SM, one wave.
#define BM 32
#define BN 64
#define BK 16

// ---------------------------------------------------------------------------
// Scratch (static device globals; no allocation allowed)
// ---------------------------------------------------------------------------
__device__ float g_ys0[S_*BH];   // encoder layer-0 outputs, all timesteps (256 MiB)
__device__ float g_Z1 [S_*BH];   // batched layer-1 input projection + biases (256 MiB)
__device__ float g_zero[BH];     // zero initial hidden state
__device__ float g_h1 [2*BH];    // encoder layer-1 hidden ping-pong
__device__ float g_hA [2*BH];    // decoder layer-0 hidden ping-pong
__device__ float g_hB [2*BH];    // decoder layer-1 hidden ping-pong
__device__ float g_inp[B_*I_];   // decoder feedback input (B x 3)

// ---------------------------------------------------------------------------
// init: zero the h0 buffer, seed decoder input = x[:, -1, :]
// ---------------------------------------------------------------------------
__global__ void k_init(const float* __restrict__ x) {
    int i = blockIdx.x * blockDim.x + threadIdx.x;
    if (i < BH) g_zero[i] = 0.0f;
    if (i < B_*I_) {
        int b = i / I_, c = i % I_;
        g_inp[i] = x[b*(S_*I_) + (S_-1)*I_ + c];
    }
}

// ---------------------------------------------------------------------------
// General RNN-step GEMM:
//   C[m][n] = epi( sum_k A[m][k]*W[n][k]  (+ sum_k A2[m][k]*W2[n][k])
//                  (+ P[m][n]) (+ xs[m][0..2] . Wsm[n][0..2]) (+ b1[n]) (+ b2[n]) )
//   epi = tanh if doTanh.
// A: M x 1024 (row-major), W: N x 1024 (row-major, i.e. computes A @ W^T).
// ---------------------------------------------------------------------------
__global__ __launch_bounds__(128) void k_gemm(
    const float* __restrict__ A,  const float* __restrict__ W,
    const float* __restrict__ A2, const float* __restrict__ W2,
    const float* __restrict__ P,
    const float* __restrict__ xs, int xs_stride, const float* __restrict__ Wsm,
    const float* __restrict__ b1, const float* __restrict__ b2,
    float* __restrict__ C, int doTanh)
{
    __shared__ __align__(16) float As[BK][BM];   // transposed: As[k][m]
    __shared__ __align__(16) float Ws[BK][BN];   // transposed: Ws[k][n]

    const int tid = threadIdx.x;
    const int tx  = tid & 15;   // 0..15 -> N direction (4 cols each)
    const int ty  = tid >> 4;   // 0..7  -> M direction (4 rows each)
    const int bn0 = blockIdx.x * BN;
    const int bm0 = blockIdx.y * BM;

    const int lc = tid & 15;    // k offset for loads (BK == 16)
    const int lr = tid >> 4;    // base row for loads

    float acc[4][4];
    #pragma unroll
    for (int i = 0; i < 4; ++i)
        #pragma unroll
        for (int j = 0; j < 4; ++j)
            acc[i][j] = 0.0f;

    const int npass = (A2 != nullptr) ? 2 : 1;
    for (int pass = 0; pass < npass; ++pass) {
        const float* __restrict__ Ap = pass ? A2 : A;
        const float* __restrict__ Wp = pass ? W2 : W;
        for (int k0 = 0; k0 < H_; k0 += BK) {
            // Load A tile (BM x BK) transposed into As: 4 elems/thread, coalesced on k.
            #pragma unroll
            for (int i = 0; i < BM/8; ++i)
                As[lc][lr + 8*i] = Ap[(bm0 + lr + 8*i)*H_ + k0 + lc];
            // Load W tile (BN x BK) transposed into Ws: 8 elems/thread.
            #pragma unroll
            for (int i = 0; i < BN/8; ++i)
                Ws[lc][lr + 8*i] = Wp[(bn0 + lr + 8*i)*H_ + k0 + lc];
            __syncthreads();

            #pragma unroll
            for (int k = 0; k < BK; ++k) {
                const float4 a4 = *(const float4*)&As[k][ty*4];
                const float4 w4 = *(const float4*)&Ws[k][tx*4];
                const float av[4] = {a4.x, a4.y, a4.z, a4.w};
                const float wv[4] = {w4.x, w4.y, w4.z, w4.w};
                #pragma unroll
                for (int i = 0; i < 4; ++i)
                    #pragma unroll
                    for (int j = 0; j < 4; ++j)
                        acc[i][j] = fmaf(av[i], wv[j], acc[i][j]);
            }
            __syncthreads();
        }
    }

    // Epilogue
    #pragma unroll
    for (int i = 0; i < 4; ++i) {
        const int row = bm0 + ty*4 + i;
        float x0 = 0.f, x1 = 0.f, x2 = 0.f;
        if (xs) {
            x0 = xs[row*xs_stride + 0];
            x1 = xs[row*xs_stride + 1];
            x2 = xs[row*xs_stride + 2];
        }
        #pragma unroll
        for (int j = 0; j < 4; ++j) {
            const int col = bn0 + tx*4 + j;
            float v = acc[i][j];
            if (P)  v += P[row*H_ + col];
            if (xs) v += x0*Wsm[col*3+0] + x1*Wsm[col*3+1] + x2*Wsm[col*3+2];
            if (b1) v += b1[col];
            if (b2) v += b2[col];
            if (doTanh) v = tanhf(v);
            C[row*H_ + col] = v;
        }
    }
}

// ---------------------------------------------------------------------------
// Decoder output head: one warp per batch row.
//   out[b][t] = hB[b,:] . Wlin + blin
//   inp[b]    = [c0, inp0 - c0, inp1 - c1]   (feedback for next step)
// ---------------------------------------------------------------------------
__global__ void k_decout(const float* __restrict__ hB,
                         const float* __restrict__ Wlin,
                         const float* __restrict__ blin,
                         float* __restrict__ out, int t)
{
    const int warp = (blockIdx.x * blockDim.x + threadIdx.x) >> 5;
    const int lane = threadIdx.x & 31;
    if (warp >= B_) return;
    const float* h = hB + warp*H_;
    float s = 0.0f;
    #pragma unroll 8
    for (int k = lane; k < H_; k += 32)
        s = fmaf(h[k], Wlin[k], s);
    #pragma unroll
    for (int off = 16; off > 0; off >>= 1)
        s += __shfl_xor_sync(0xffffffffu, s, off);
    if (lane == 0) {
        const float o = s + blin[0];
        out[warp*T_ + t] = o;
        const float i0 = g_inp[warp*3 + 0];
        const float i1 = g_inp[warp*3 + 1];
        const float c0 = o;
        const float c1 = i0 - c0;
        const float c2 = i1 - c1;
        g_inp[warp*3 + 0] = c0;
        g_inp[warp*3 + 1] = c1;
        g_inp[warp*3 + 2] = c2;
    }
}

// ---------------------------------------------------------------------------
// Orchestration (graph-capturable: kernel launches only, default stream)
// ---------------------------------------------------------------------------
extern "C" void kernel_launch(void* const* d_in, const int* in_sizes, int n_in,
                              void* d_out, int out_size)
{
    (void)in_sizes; (void)n_in; (void)out_size;
    const float* x     = (const float*)d_in[0];
    // d_in[1] = y : unused (teacher_forcing_ratio == 0)
    const float* eWih0 = (const float*)d_in[2];
    const float* eWhh0 = (const float*)d_in[3];
    const float* ebih0 = (const float*)d_in[4];
    const float* ebhh0 = (const float*)d_in[5];
    const float* eWih1 = (const float*)d_in[6];
    const float* eWhh1 = (const float*)d_in[7];
    const float* ebih1 = (const float*)d_in[8];
    const float* ebhh1 = (const float*)d_in[9];
    const float* dWih0 = (const float*)d_in[10];
    const float* dWhh0 = (const float*)d_in[11];
    const float* dbih0 = (const float*)d_in[12];
    const float* dbhh0 = (const float*)d_in[13];
    const float* dWih1 = (const float*)d_in[14];
    const float* dWhh1 = (const float*)d_in[15];
    const float* dbih1 = (const float*)d_in[16];
    const float* dbhh1 = (const float*)d_in[17];
    const float* dWlin = (const float*)d_in[18];
    const float* dblin = (const float*)d_in[19];
    float* out = (float*)d_out;

    float *ys0, *Z1, *zero, *h1, *hA, *hB, *inp;
    cudaGetSymbolAddress((void**)&ys0,  g_ys0);
    cudaGetSymbolAddress((void**)&Z1,   g_Z1);
    cudaGetSymbolAddress((void**)&zero, g_zero);
    cudaGetSymbolAddress((void**)&h1,   g_h1);
    cudaGetSymbolAddress((void**)&hA,   g_hA);
    cudaGetSymbolAddress((void**)&hB,   g_hB);
    cudaGetSymbolAddress((void**)&inp,  g_inp);

    k_init<<<(BH + 255)/256, 256>>>(x);

    const dim3 blk(128);
    const dim3 gstep(H_/BN, B_/BM);         // (16, 8)   = 128 blocks
    const dim3 gbig (H_/BN, (S_*B_)/BM);    // (16, 2048)

    // ---- Encoder layer 0 (sequential; x-projection fused in epilogue) ----
    for (int t = 0; t < S_; ++t) {
        const float* Ain = (t == 0) ? zero : (ys0 + (t-1)*BH);
        k_gemm<<<gstep, blk>>>(Ain, eWhh0, nullptr, nullptr, nullptr,
                               x + t*I_, S_*I_, eWih0, ebih0, ebhh0,
                               ys0 + t*BH, 1);
    }

    // ---- Batched layer-1 input projection: Z1 = ys0 @ Wih1^T + bih1 + bhh1 ----
    k_gemm<<<gbig, blk>>>(ys0, eWih1, nullptr, nullptr, nullptr,
                          nullptr, 0, nullptr, ebih1, ebhh1,
                          Z1, 0);

    // ---- Encoder layer 1 recurrence (sequential, Z1 precomputed) ----
    for (int t = 0; t < S_; ++t) {
        const float* Ain = (t == 0) ? zero : (h1 + ((t-1)&1)*BH);
        k_gemm<<<gstep, blk>>>(Ain, eWhh1, nullptr, nullptr, Z1 + t*BH,
                               nullptr, 0, nullptr, nullptr, nullptr,
                               h1 + (t&1)*BH, 1);
    }

    // ---- Decoder: 64 sequential steps ----
    const float* hA_prev = ys0 + (S_-1)*BH;        // h_enc0
    const float* hB_prev = h1 + ((S_-1)&1)*BH;     // h_enc1
    for (int t = 0; t < T_; ++t) {
        float* hA_new = hA + (t&1)*BH;
        // hA = tanh(inp @ dWih0^T + dbih0 + hA @ dWhh0^T + dbhh0)
        k_gemm<<<gstep, blk>>>(hA_prev, dWhh0, nullptr, nullptr, nullptr,
                               inp, I_, dWih0, dbih0, dbhh0,
                               hA_new, 1);
        float* hB_new = hB + (t&1)*BH;
        // hB = tanh(hA_new @ dWih1^T + dbih1 + hB @ dWhh1^T + dbhh1)  (K=2048 fused)
        k_gemm<<<gstep, blk>>>(hA_new, dWih1, hB_prev, dWhh1, nullptr,
                               nullptr, 0, nullptr, dbih1, dbhh1,
                               hB_new, 1);
        // out + feedback update
        k_decout<<<32, 256>>>(hB_new, dWlin, dblin, out, t);
        hA_prev = hA_new;
        hB_prev = hB_new;
    }
}

// round 5
// speedup vs baseline: 3.8185x; 3.8185x over previous
#include <cuda_runtime.h>
#include <cuda_bf16.h>
#include <stdint.h>
#include <math.h>

// Problem dims (fixed)
#define B_ 256
#define S_ 256
#define I_ 3
#define H_ 1024
#define T_ 64
#define BH (B_*H_)

// GEMM tiling: 32x64 tile per CTA, BK=64 bf16 k-chunks, 128 threads (4 warps),
// each warp computes the full 32 rows x a 16-col slice via 4x m16n8k16 mma.
#define BM 32
#define BN 64
#define BK 64
#define NSTAGE 4
#define KCH (H_/BK)      // 16 k-chunks per pass

// ---------------------------------------------------------------------------
// Device scratch (no allocation allowed)
// ---------------------------------------------------------------------------
__device__ __nv_bfloat16 g_ys0_hi[S_*BH];    // enc layer-0 outputs (hi)
__device__ __nv_bfloat16 g_ys0_lo[S_*BH];    // enc layer-0 outputs (lo)
__device__ float         g_Z1[S_*BH];        // layer-1 input projection (fp32)
__device__ __nv_bfloat16 g_h1hi[2*BH], g_h1lo[2*BH];
__device__ __nv_bfloat16 g_hAhi[2*BH], g_hAlo[2*BH];
__device__ __nv_bfloat16 g_hBhi[2*BH], g_hBlo[2*BH];
__device__ __nv_bfloat16 g_zb[BH];           // zero hidden state (hi & lo)
__device__ float         g_inp[B_*I_];       // decoder feedback input
// 6 H x H weights as bf16 hi/lo: 0:eWhh0 1:eWih1 2:eWhh1 3:dWhh0 4:dWih1 5:dWhh1
__device__ __nv_bfloat16 g_Whi[6][H_*H_];
__device__ __nv_bfloat16 g_Wlo[6][H_*H_];

// ---------------------------------------------------------------------------
__global__ void k_init(const float* __restrict__ x) {
    int i = blockIdx.x * blockDim.x + threadIdx.x;
    if (i < BH) g_zb[i] = __float2bfloat16(0.0f);
    if (i < B_*I_) {
        int b = i / I_, c = i % I_;
        g_inp[i] = x[b*(S_*I_) + (S_-1)*I_ + c];
    }
}

__global__ void k_conv(const float* __restrict__ src,
                       __nv_bfloat16* __restrict__ hi,
                       __nv_bfloat16* __restrict__ lo, int n) {
    int i = blockIdx.x * blockDim.x + threadIdx.x;
    if (i < n) {
        float v = src[i];
        __nv_bfloat16 h = __float2bfloat16(v);
        hi[i] = h;
        lo[i] = __float2bfloat16(v - __bfloat162float(h));
    }
}

// ---------------------------------------------------------------------------
// Tensor-core RNN-step GEMM with bf16 hi/lo split (3 passes per A/W set):
//   C = epi( A @ W^T  (+ A2 @ W2^T)  (+ P) (+ xs . Wsm^T) (+ b1) (+ b2) )
// A given as (Ahi, Alo), W as (Whi, Wlo); passes (hi,hi),(hi,lo),(lo,hi).
// Output: fp32 (Cf) or tanh + bf16 hi/lo (Chi/Clo).
// ---------------------------------------------------------------------------
__global__ __launch_bounds__(128) void k_mma(
    const __nv_bfloat16* __restrict__ Ahi0, const __nv_bfloat16* __restrict__ Alo0,
    const __nv_bfloat16* __restrict__ Whi0, const __nv_bfloat16* __restrict__ Wlo0,
    const __nv_bfloat16* __restrict__ Ahi1, const __nv_bfloat16* __restrict__ Alo1,
    const __nv_bfloat16* __restrict__ Whi1, const __nv_bfloat16* __restrict__ Wlo1,
    int nsets,
    const float* __restrict__ P,
    const float* __restrict__ xs, int xs_stride, const float* __restrict__ Wsm,
    const float* __restrict__ b1, const float* __restrict__ b2,
    float* __restrict__ Cf,
    __nv_bfloat16* __restrict__ Chi, __nv_bfloat16* __restrict__ Clo,
    int doTanh)
{
    // XOR-swizzled (8-half granularity), no padding: exactly 48KB.
    __shared__ __align__(16) __nv_bfloat16 As[NSTAGE][BM][BK];
    __shared__ __align__(16) __nv_bfloat16 Bs[NSTAGE][BN][BK];

    const int tid  = threadIdx.x;
    const int lane = tid & 31;
    const int w    = tid >> 5;
    const int bm0  = blockIdx.y * BM;
    const int bn0  = blockIdx.x * BN;

    const int lrow  = tid >> 3;        // 0..15
    const int lcolh = (tid & 7) * 8;   // 16B chunk (halves)

    const int NC = nsets * 3 * KCH;

    auto prefetch = [&](int c, int slot) {
        int s   = c / (3*KCH);
        int rem = c - s*(3*KCH);
        int p   = rem >> 4;            // KCH == 16
        int k0  = (rem & 15) * BK;
        const __nv_bfloat16* Ap = (s == 0) ? (p < 2 ? Ahi0 : Alo0)
                                           : (p < 2 ? Ahi1 : Alo1);
        const __nv_bfloat16* Wp = (s == 0) ? (p == 1 ? Wlo0 : Whi0)
                                           : (p == 1 ? Wlo1 : Whi1);
        #pragma unroll
        for (int i = 0; i < 2; ++i) {
            int r  = lrow + 16*i;
            int sc = lcolh ^ ((r & 7) * 8);
            uint32_t dst = (uint32_t)__cvta_generic_to_shared(&As[slot][r][sc]);
            const void* src = Ap + (size_t)(bm0 + r)*H_ + k0 + lcolh;
            asm volatile("cp.async.cg.shared.global [%0], [%1], 16;\n"
                         :: "r"(dst), "l"(src));
        }
        #pragma unroll
        for (int i = 0; i < 4; ++i) {
            int r  = lrow + 16*i;
            int sc = lcolh ^ ((r & 7) * 8);
            uint32_t dst = (uint32_t)__cvta_generic_to_shared(&Bs[slot][r][sc]);
            const void* src = Wp + (size_t)(bn0 + r)*H_ + k0 + lcolh;
            asm volatile("cp.async.cg.shared.global [%0], [%1], 16;\n"
                         :: "r"(dst), "l"(src));
        }
    };

    float acc[2][2][4];
    #pragma unroll
    for (int mi = 0; mi < 2; ++mi)
        #pragma unroll
        for (int ni = 0; ni < 2; ++ni)
            #pragma unroll
            for (int q = 0; q < 4; ++q) acc[mi][ni][q] = 0.0f;

    prefetch(0, 0); asm volatile("cp.async.commit_group;");
    prefetch(1, 1); asm volatile("cp.async.commit_group;");
    prefetch(2, 2); asm volatile("cp.async.commit_group;");

    for (int c = 0; c < NC; ++c) {
        asm volatile("cp.async.wait_group 2;");
        __syncthreads();                 // data visible + slot (c-1)&3 free
        if (c + 3 < NC) prefetch(c + 3, (c + 3) & 3);
        asm volatile("cp.async.commit_group;");

        const int slot = c & 3;
        #pragma unroll
        for (int k16 = 0; k16 < BK/16; ++k16) {
            const int kh = k16 * 16;
            uint32_t a[2][4];
            #pragma unroll
            for (int h = 0; h < 2; ++h) {
                int r = h*16 + (lane & 15);
                int cc = (kh + ((lane >> 4) * 8)) ^ ((r & 7) * 8);
                uint32_t addr = (uint32_t)__cvta_generic_to_shared(&As[slot][r][cc]);
                asm volatile("ldmatrix.sync.aligned.m8n8.x4.shared.b16 {%0,%1,%2,%3}, [%4];"
                    : "=r"(a[h][0]), "=r"(a[h][1]), "=r"(a[h][2]), "=r"(a[h][3])
                    : "r"(addr));
            }
            uint32_t b[4];
            {
                int j = lane >> 3;
                int r = w*16 + ((j >> 1) * 8) + (lane & 7);
                int cc = (kh + (j & 1) * 8) ^ ((r & 7) * 8);
                uint32_t addr = (uint32_t)__cvta_generic_to_shared(&Bs[slot][r][cc]);
                asm volatile("ldmatrix.sync.aligned.m8n8.x4.shared.b16 {%0,%1,%2,%3}, [%4];"
                    : "=r"(b[0]), "=r"(b[1]), "=r"(b[2]), "=r"(b[3])
                    : "r"(addr));
            }
            #pragma unroll
            for (int mi = 0; mi < 2; ++mi)
                #pragma unroll
                for (int ni = 0; ni < 2; ++ni)
                    asm volatile(
                        "mma.sync.aligned.m16n8k16.row.col.f32.bf16.bf16.f32 "
                        "{%0,%1,%2,%3}, {%4,%5,%6,%7}, {%8,%9}, {%0,%1,%2,%3};"
                        : "+f"(acc[mi][ni][0]), "+f"(acc[mi][ni][1]),
                          "+f"(acc[mi][ni][2]), "+f"(acc[mi][ni][3])
                        : "r"(a[mi][0]), "r"(a[mi][1]), "r"(a[mi][2]), "r"(a[mi][3]),
                          "r"(b[2*ni]), "r"(b[2*ni+1]));
        }
    }

    // Epilogue. acc d0,d1 -> row=lane/4, cols 2*(lane&3)+{0,1}; d2,d3 -> row+8.
    #pragma unroll
    for (int mi = 0; mi < 2; ++mi) {
        #pragma unroll
        for (int h = 0; h < 2; ++h) {
            const int row = bm0 + mi*16 + (lane >> 2) + h*8;
            float x0 = 0.f, x1 = 0.f, x2 = 0.f;
            if (xs) {
                const float* xr = xs + (size_t)row * xs_stride;
                x0 = xr[0]; x1 = xr[1]; x2 = xr[2];
            }
            #pragma unroll
            for (int ni = 0; ni < 2; ++ni) {
                const int col = bn0 + w*16 + ni*8 + (lane & 3)*2;
                float v0 = acc[mi][ni][h*2 + 0];
                float v1 = acc[mi][ni][h*2 + 1];
                if (P) {
                    const float* pr = P + (size_t)row*H_ + col;
                    v0 += pr[0]; v1 += pr[1];
                }
                if (xs) {
                    v0 += x0*Wsm[col*3+0] + x1*Wsm[col*3+1] + x2*Wsm[col*3+2];
                    v1 += x0*Wsm[(col+1)*3+0] + x1*Wsm[(col+1)*3+1] + x2*Wsm[(col+1)*3+2];
                }
                if (b1) { v0 += b1[col]; v1 += b1[col+1]; }
                if (b2) { v0 += b2[col]; v1 += b2[col+1]; }
                if (doTanh) { v0 = tanhf(v0); v1 = tanhf(v1); }
                const size_t off = (size_t)row*H_ + col;
                if (Cf) {
                    *(float2*)(Cf + off) = make_float2(v0, v1);
                }
                if (Chi) {
                    __nv_bfloat16 h0 = __float2bfloat16(v0);
                    __nv_bfloat16 h1 = __float2bfloat16(v1);
                    __nv_bfloat16 l0 = __float2bfloat16(v0 - __bfloat162float(h0));
                    __nv_bfloat16 l1 = __float2bfloat16(v1 - __bfloat162float(h1));
                    *(__nv_bfloat162*)(Chi + off) = __halves2bfloat162(h0, h1);
                    *(__nv_bfloat162*)(Clo + off) = __halves2bfloat162(l0, l1);
                }
            }
        }
    }
}

// ---------------------------------------------------------------------------
// Decoder output head: one warp per batch row; reads bf16 hi/lo hidden.
// ---------------------------------------------------------------------------
__global__ void k_decout(const __nv_bfloat16* __restrict__ hhi,
                         const __nv_bfloat16* __restrict__ hlo,
                         const float* __restrict__ Wlin,
                         const float* __restrict__ blin,
                         float* __restrict__ out, int t)
{
    const int warp = (blockIdx.x * blockDim.x + threadIdx.x) >> 5;
    const int lane = threadIdx.x & 31;
    if (warp >= B_) return;
    const __nv_bfloat16* hh = hhi + warp*H_;
    const __nv_bfloat16* hl = hlo + warp*H_;
    float s = 0.0f;
    #pragma unroll 8
    for (int k = lane; k < H_; k += 32) {
        float hv = __bfloat162float(hh[k]) + __bfloat162float(hl[k]);
        s = fmaf(hv, Wlin[k], s);
    }
    #pragma unroll
    for (int off = 16; off > 0; off >>= 1)
        s += __shfl_xor_sync(0xffffffffu, s, off);
    if (lane == 0) {
        const float o = s + blin[0];
        out[warp*T_ + t] = o;
        const float i0 = g_inp[warp*3 + 0];
        const float i1 = g_inp[warp*3 + 1];
        const float c0 = o;
        const float c1 = i0 - c0;
        const float c2 = i1 - c1;
        g_inp[warp*3 + 0] = c0;
        g_inp[warp*3 + 1] = c1;
        g_inp[warp*3 + 2] = c2;
    }
}

// ---------------------------------------------------------------------------
// Orchestration (graph-capturable: kernel launches only, default stream)
// ---------------------------------------------------------------------------
extern "C" void kernel_launch(void* const* d_in, const int* in_sizes, int n_in,
                              void* d_out, int out_size)
{
    (void)in_sizes; (void)n_in; (void)out_size;
    const float* x     = (const float*)d_in[0];
    const float* eWih0 = (const float*)d_in[2];
    const float* eWhh0 = (const float*)d_in[3];
    const float* ebih0 = (const float*)d_in[4];
    const float* ebhh0 = (const float*)d_in[5];
    const float* eWih1 = (const float*)d_in[6];
    const float* eWhh1 = (const float*)d_in[7];
    const float* ebih1 = (const float*)d_in[8];
    const float* ebhh1 = (const float*)d_in[9];
    const float* dWih0 = (const float*)d_in[10];
    const float* dWhh0 = (const float*)d_in[11];
    const float* dbih0 = (const float*)d_in[12];
    const float* dbhh0 = (const float*)d_in[13];
    const float* dWih1 = (const float*)d_in[14];
    const float* dWhh1 = (const float*)d_in[15];
    const float* dbih1 = (const float*)d_in[16];
    const float* dbhh1 = (const float*)d_in[17];
    const float* dWlin = (const float*)d_in[18];
    const float* dblin = (const float*)d_in[19];
    float* out = (float*)d_out;

    __nv_bfloat16 *ys0hi, *ys0lo, *h1hi, *h1lo, *hAhi, *hAlo, *hBhi, *hBlo, *zb, *Whi, *Wlo;
    float *Z1, *inp;
    cudaGetSymbolAddress((void**)&ys0hi, g_ys0_hi);
    cudaGetSymbolAddress((void**)&ys0lo, g_ys0_lo);
    cudaGetSymbolAddress((void**)&Z1,    g_Z1);
    cudaGetSymbolAddress((void**)&h1hi,  g_h1hi);
    cudaGetSymbolAddress((void**)&h1lo,  g_h1lo);
    cudaGetSymbolAddress((void**)&hAhi,  g_hAhi);
    cudaGetSymbolAddress((void**)&hAlo,  g_hAlo);
    cudaGetSymbolAddress((void**)&hBhi,  g_hBhi);
    cudaGetSymbolAddress((void**)&hBlo,  g_hBlo);
    cudaGetSymbolAddress((void**)&zb,    g_zb);
    cudaGetSymbolAddress((void**)&inp,   g_inp);
    cudaGetSymbolAddress((void**)&Whi,   g_Whi);
    cudaGetSymbolAddress((void**)&Wlo,   g_Wlo);

    const int HH = H_*H_;
    auto WHI = [&](int i){ return Whi + (size_t)i*HH; };
    auto WLO = [&](int i){ return Wlo + (size_t)i*HH; };

    k_init<<<(BH + 255)/256, 256>>>(x);

    // Weight conversion (order: eWhh0, eWih1, eWhh1, dWhh0, dWih1, dWhh1)
    const float* wsrc[6] = {eWhh0, eWih1, eWhh1, dWhh0, dWih1, dWhh1};
    for (int i = 0; i < 6; ++i)
        k_conv<<<HH/256, 256>>>(wsrc[i], WHI(i), WLO(i), HH);

    const dim3 blk(128);
    const dim3 gstep(H_/BN, B_/BM);        // (16, 8) = 128 CTAs
    const dim3 gbig (H_/BN, (S_*B_)/BM);   // (16, 2048)

    // ---- Encoder layer 0 (sequential; x-projection fused in epilogue) ----
    for (int t = 0; t < S_; ++t) {
        const __nv_bfloat16* Ah = t ? (ys0hi + (size_t)(t-1)*BH) : zb;
        const __nv_bfloat16* Al = t ? (ys0lo + (size_t)(t-1)*BH) : zb;
        k_mma<<<gstep, blk>>>(Ah, Al, WHI(0), WLO(0),
                              nullptr, nullptr, nullptr, nullptr, 1,
                              nullptr, x + t*I_, S_*I_, eWih0, ebih0, ebhh0,
                              nullptr, ys0hi + (size_t)t*BH, ys0lo + (size_t)t*BH, 1);
    }

    // ---- Batched: Z1 = ys0 @ eWih1^T + bih1 + bhh1 (fp32, no tanh) ----
    k_mma<<<gbig, blk>>>(ys0hi, ys0lo, WHI(1), WLO(1),
                         nullptr, nullptr, nullptr, nullptr, 1,
                         nullptr, nullptr, 0, nullptr, ebih1, ebhh1,
                         Z1, nullptr, nullptr, 0);

    // ---- Encoder layer 1 recurrence ----
    for (int t = 0; t < S_; ++t) {
        const __nv_bfloat16* Ah = t ? (h1hi + ((t-1)&1)*BH) : zb;
        const __nv_bfloat16* Al = t ? (h1lo + ((t-1)&1)*BH) : zb;
        k_mma<<<gstep, blk>>>(Ah, Al, WHI(2), WLO(2),
                              nullptr, nullptr, nullptr, nullptr, 1,
                              Z1 + (size_t)t*BH, nullptr, 0, nullptr, nullptr, nullptr,
                              nullptr, h1hi + (t&1)*BH, h1lo + (t&1)*BH, 1);
    }

    // ---- Decoder: 64 sequential steps ----
    const __nv_bfloat16* hAp_hi = ys0hi + (size_t)(S_-1)*BH;
    const __nv_bfloat16* hAp_lo = ys0lo + (size_t)(S_-1)*BH;
    const __nv_bfloat16* hBp_hi = h1hi + ((S_-1)&1)*BH;
    const __nv_bfloat16* hBp_lo = h1lo + ((S_-1)&1)*BH;
    for (int t = 0; t < T_; ++t) {
        __nv_bfloat16* hA_hi = hAhi + (t&1)*BH;
        __nv_bfloat16* hA_lo = hAlo + (t&1)*BH;
        k_mma<<<gstep, blk>>>(hAp_hi, hAp_lo, WHI(3), WLO(3),
                              nullptr, nullptr, nullptr, nullptr, 1,
                              nullptr, inp, I_, dWih0, dbih0, dbhh0,
                              nullptr, hA_hi, hA_lo, 1);
        __nv_bfloat16* hB_hi = hBhi + (t&1)*BH;
        __nv_bfloat16* hB_lo = hBlo + (t&1)*BH;
        // hB = tanh(hA @ dWih1^T + hB_prev @ dWhh1^T + biases), K=2048 fused
        k_mma<<<gstep, blk>>>(hA_hi, hA_lo, WHI(4), WLO(4),
                              hBp_hi, hBp_lo, WHI(5), WLO(5), 2,
                              nullptr, nullptr, 0, nullptr, dbih1, dbhh1,
                              nullptr, hB_hi, hB_lo, 1);
        k_decout<<<32, 256>>>(hB_hi, hB_lo, dWlin, dblin, out, t);
        hAp_hi = hA_hi; hAp_lo = hA_lo;
        hBp_hi = hB_hi; hBp_lo = hB_lo;
    }
}

// round 6
// speedup vs baseline: 7.9560x; 2.0836x over previous
#include <cuda_runtime.h>
#include <cuda_fp16.h>
#include <stdint.h>
#include <math.h>

// Problem dims (fixed)
#define B_ 256
#define S_ 256
#define I_ 3
#define H_ 1024
#define T_ 64
#define BH (B_*H_)

// GEMM tiling: 32x64 tile per CTA, BK=64 k-chunk. 128 threads (4 warps).
// Each chunk holds A_hi, A_lo and W tiles; both hi*W and lo*W products are
// computed against the SAME W tile (W traffic halved vs separate passes).
#define BM 32
#define BN 64
#define BK 64
#define NSTAGE 3
#define KCH 16            // k-chunks per K=1024
#define CH 32             // encoder pipeline chunk (timesteps)
#define NCH (S_/CH)       // 8

// ---------------------------------------------------------------------------
// Device scratch (no allocation allowed)
// ---------------------------------------------------------------------------
__device__ __half g_ys0_hi[S_*BH];   // enc layer-0 outputs (fp16 hi)
__device__ __half g_ys0_lo[S_*BH];   // enc layer-0 outputs (fp16 lo residual)
__device__ float  g_Z1[S_*BH];       // layer-1 input projection (fp32)
__device__ __half g_h1hi[2*BH], g_h1lo[2*BH];
__device__ __half g_hAhi[2*BH], g_hAlo[2*BH];
__device__ __half g_hBhi[2*BH], g_hBlo[2*BH];
__device__ __half g_zb[BH];          // zero hidden state
__device__ float  g_inp[B_*I_];      // decoder feedback input
// 6 H x H weights as single fp16: 0:eWhh0 1:eWih1 2:eWhh1 3:dWhh0 4:dWih1 5:dWhh1
__device__ __half g_W[6][H_*H_];

// ---------------------------------------------------------------------------
__global__ void k_init(const float* __restrict__ x) {
    int i = blockIdx.x * blockDim.x + threadIdx.x;
    if (i < BH) g_zb[i] = __float2half(0.0f);
    if (i < B_*I_) {
        int b = i / I_, c = i % I_;
        g_inp[i] = x[b*(S_*I_) + (S_-1)*I_ + c];
    }
}

__global__ void k_conv(const float* __restrict__ src,
                       __half* __restrict__ dst, int n) {
    int i = blockIdx.x * blockDim.x + threadIdx.x;
    if (i < n) dst[i] = __float2half(src[i]);
}

// ---------------------------------------------------------------------------
// Tensor-core RNN-step GEMM, fp16 2-product scheme:
//   C = epi( (Ahi+Alo) @ W^T  (+ (A2hi+A2lo) @ W2^T)
//            (+ P) (+ xs . Wsm^T) (+ b1) (+ b2) )
// Output: fp32 (Cf) or tanh + fp16 hi/lo (Chi/Clo).
// ---------------------------------------------------------------------------
__global__ __launch_bounds__(128) void k_mma(
    const __half* __restrict__ Ahi0, const __half* __restrict__ Alo0,
    const __half* __restrict__ W0,
    const __half* __restrict__ Ahi1, const __half* __restrict__ Alo1,
    const __half* __restrict__ W1,
    int nsets,
    const float* __restrict__ P,
    const float* __restrict__ xs, int xs_stride, const float* __restrict__ Wsm,
    const float* __restrict__ b1, const float* __restrict__ b2,
    float* __restrict__ Cf,
    __half* __restrict__ Chi, __half* __restrict__ Clo,
    int doTanh)
{
    // 3 stages x (4KB + 4KB + 8KB) = 48KB exactly. XOR swizzle, 16B granule.
    __shared__ __align__(16) __half Ah_s[NSTAGE][BM][BK];
    __shared__ __align__(16) __half Al_s[NSTAGE][BM][BK];
    __shared__ __align__(16) __half Ws_s[NSTAGE][BN][BK];

    const int tid  = threadIdx.x;
    const int lane = tid & 31;
    const int w    = tid >> 5;
    const int bm0  = blockIdx.y * BM;
    const int bn0  = blockIdx.x * BN;

    const int lrow  = tid >> 3;        // 0..15
    const int lcolh = (tid & 7) * 8;   // 16B chunk in halves

    const int NC = nsets * KCH;

    auto prefetch = [&](int c, int slot) {
        int s  = c >> 4;               // set index (KCH == 16)
        int k0 = (c & 15) * BK;
        const __half* Ah = s ? Ahi1 : Ahi0;
        const __half* Al = s ? Alo1 : Alo0;
        const __half* Wp = s ? W1   : W0;
        #pragma unroll
        for (int i = 0; i < 2; ++i) {
            int r  = lrow + 16*i;
            int sc = lcolh ^ ((r & 7) * 8);
            uint32_t d1 = (uint32_t)__cvta_generic_to_shared(&Ah_s[slot][r][sc]);
            const void* s1 = Ah + (size_t)(bm0 + r)*H_ + k0 + lcolh;
            asm volatile("cp.async.cg.shared.global [%0], [%1], 16;\n" :: "r"(d1), "l"(s1));
            uint32_t d2 = (uint32_t)__cvta_generic_to_shared(&Al_s[slot][r][sc]);
            const void* s2 = Al + (size_t)(bm0 + r)*H_ + k0 + lcolh;
            asm volatile("cp.async.cg.shared.global [%0], [%1], 16;\n" :: "r"(d2), "l"(s2));
        }
        #pragma unroll
        for (int i = 0; i < 4; ++i) {
            int r  = lrow + 16*i;
            int sc = lcolh ^ ((r & 7) * 8);
            uint32_t d3 = (uint32_t)__cvta_generic_to_shared(&Ws_s[slot][r][sc]);
            const void* s3 = Wp + (size_t)(bn0 + r)*H_ + k0 + lcolh;
            asm volatile("cp.async.cg.shared.global [%0], [%1], 16;\n" :: "r"(d3), "l"(s3));
        }
    };

    float acc[2][2][4];
    #pragma unroll
    for (int mi = 0; mi < 2; ++mi)
        #pragma unroll
        for (int ni = 0; ni < 2; ++ni)
            #pragma unroll
            for (int q = 0; q < 4; ++q) acc[mi][ni][q] = 0.0f;

    prefetch(0, 0); asm volatile("cp.async.commit_group;");
    if (NC > 1) prefetch(1, 1);
    asm volatile("cp.async.commit_group;");

    for (int c = 0; c < NC; ++c) {
        asm volatile("cp.async.wait_group 1;");
        __syncthreads();
        if (c + 2 < NC) prefetch(c + 2, (c + 2) % 3);
        asm volatile("cp.async.commit_group;");

        const int slot = c % 3;
        #pragma unroll
        for (int k16 = 0; k16 < BK/16; ++k16) {
            const int kh = k16 * 16;
            uint32_t ah[2][4], al[2][4];
            #pragma unroll
            for (int h = 0; h < 2; ++h) {
                int r  = h*16 + (lane & 15);
                int cc = (kh + ((lane >> 4) * 8)) ^ ((r & 7) * 8);
                uint32_t a1 = (uint32_t)__cvta_generic_to_shared(&Ah_s[slot][r][cc]);
                asm volatile("ldmatrix.sync.aligned.m8n8.x4.shared.b16 {%0,%1,%2,%3}, [%4];"
                    : "=r"(ah[h][0]), "=r"(ah[h][1]), "=r"(ah[h][2]), "=r"(ah[h][3]) : "r"(a1));
                uint32_t a2 = (uint32_t)__cvta_generic_to_shared(&Al_s[slot][r][cc]);
                asm volatile("ldmatrix.sync.aligned.m8n8.x4.shared.b16 {%0,%1,%2,%3}, [%4];"
                    : "=r"(al[h][0]), "=r"(al[h][1]), "=r"(al[h][2]), "=r"(al[h][3]) : "r"(a2));
            }
            uint32_t b[4];
            {
                int j  = lane >> 3;
                int r  = w*16 + ((j >> 1) * 8) + (lane & 7);
                int cc = (kh + (j & 1) * 8) ^ ((r & 7) * 8);
                uint32_t addr = (uint32_t)__cvta_generic_to_shared(&Ws_s[slot][r][cc]);
                asm volatile("ldmatrix.sync.aligned.m8n8.x4.shared.b16 {%0,%1,%2,%3}, [%4];"
                    : "=r"(b[0]), "=r"(b[1]), "=r"(b[2]), "=r"(b[3]) : "r"(addr));
            }
            #pragma unroll
            for (int mi = 0; mi < 2; ++mi)
                #pragma unroll
                for (int ni = 0; ni < 2; ++ni) {
                    asm volatile(
                        "mma.sync.aligned.m16n8k16.row.col.f32.f16.f16.f32 "
                        "{%0,%1,%2,%3}, {%4,%5,%6,%7}, {%8,%9}, {%0,%1,%2,%3};"
                        : "+f"(acc[mi][ni][0]), "+f"(acc[mi][ni][1]),
                          "+f"(acc[mi][ni][2]), "+f"(acc[mi][ni][3])
                        : "r"(ah[mi][0]), "r"(ah[mi][1]), "r"(ah[mi][2]), "r"(ah[mi][3]),
                          "r"(b[2*ni]), "r"(b[2*ni+1]));
                    asm volatile(
                        "mma.sync.aligned.m16n8k16.row.col.f32.f16.f16.f32 "
                        "{%0,%1,%2,%3}, {%4,%5,%6,%7}, {%8,%9}, {%0,%1,%2,%3};"
                        : "+f"(acc[mi][ni][0]), "+f"(acc[mi][ni][1]),
                          "+f"(acc[mi][ni][2]), "+f"(acc[mi][ni][3])
                        : "r"(al[mi][0]), "r"(al[mi][1]), "r"(al[mi][2]), "r"(al[mi][3]),
                          "r"(b[2*ni]), "r"(b[2*ni+1]));
                }
        }
    }

    // Epilogue. acc d0,d1 -> row=lane/4, cols 2*(lane&3)+{0,1}; d2,d3 -> row+8.
    #pragma unroll
    for (int mi = 0; mi < 2; ++mi) {
        #pragma unroll
        for (int h = 0; h < 2; ++h) {
            const int row = bm0 + mi*16 + (lane >> 2) + h*8;
            float x0 = 0.f, x1 = 0.f, x2 = 0.f;
            if (xs) {
                const float* xr = xs + (size_t)row * xs_stride;
                x0 = xr[0]; x1 = xr[1]; x2 = xr[2];
            }
            #pragma unroll
            for (int ni = 0; ni < 2; ++ni) {
                const int col = bn0 + w*16 + ni*8 + (lane & 3)*2;
                float v0 = acc[mi][ni][h*2 + 0];
                float v1 = acc[mi][ni][h*2 + 1];
                if (P) {
                    const float* pr = P + (size_t)row*H_ + col;
                    v0 += pr[0]; v1 += pr[1];
                }
                if (xs) {
                    v0 += x0*Wsm[col*3+0] + x1*Wsm[col*3+1] + x2*Wsm[col*3+2];
                    v1 += x0*Wsm[(col+1)*3+0] + x1*Wsm[(col+1)*3+1] + x2*Wsm[(col+1)*3+2];
                }
                if (b1) { v0 += b1[col]; v1 += b1[col+1]; }
                if (b2) { v0 += b2[col]; v1 += b2[col+1]; }
                if (doTanh) { v0 = tanhf(v0); v1 = tanhf(v1); }
                const size_t off = (size_t)row*H_ + col;
                if (Cf) {
                    *(float2*)(Cf + off) = make_float2(v0, v1);
                }
                if (Chi) {
                    __half h0 = __float2half(v0);
                    __half h1 = __float2half(v1);
                    __half l0 = __float2half(v0 - __half2float(h0));
                    __half l1 = __float2half(v1 - __half2float(h1));
                    *(__half2*)(Chi + off) = __halves2half2(h0, h1);
                    *(__half2*)(Clo + off) = __halves2half2(l0, l1);
                }
            }
        }
    }
}

// ---------------------------------------------------------------------------
// Decoder output head: one warp per batch row; reads fp16 hi/lo hidden.
// ---------------------------------------------------------------------------
__global__ void k_decout(const __half* __restrict__ hhi,
                         const __half* __restrict__ hlo,
                         const float* __restrict__ Wlin,
                         const float* __restrict__ blin,
                         float* __restrict__ out, int t)
{
    const int warp = (blockIdx.x * blockDim.x + threadIdx.x) >> 5;
    const int lane = threadIdx.x & 31;
    if (warp >= B_) return;
    const __half* hh = hhi + warp*H_;
    const __half* hl = hlo + warp*H_;
    float s = 0.0f;
    #pragma unroll 8
    for (int k = lane; k < H_; k += 32) {
        float hv = __half2float(hh[k]) + __half2float(hl[k]);
        s = fmaf(hv, Wlin[k], s);
    }
    #pragma unroll
    for (int off = 16; off > 0; off >>= 1)
        s += __shfl_xor_sync(0xffffffffu, s, off);
    if (lane == 0) {
        const float o = s + blin[0];
        out[warp*T_ + t] = o;
        const float i0 = g_inp[warp*3 + 0];
        const float i1 = g_inp[warp*3 + 1];
        const float c0 = o;
        const float c1 = i0 - c0;
        const float c2 = i1 - c1;
        g_inp[warp*3 + 0] = c0;
        g_inp[warp*3 + 1] = c1;
        g_inp[warp*3 + 2] = c2;
    }
}

// ---------------------------------------------------------------------------
// Orchestration. Graph-capturable: kernel launches + event fork/join only.
// enc0 chain (stream sA) and Z1-chunks + enc1 chain (stream sB) overlap.
// ---------------------------------------------------------------------------
extern "C" void kernel_launch(void* const* d_in, const int* in_sizes, int n_in,
                              void* d_out, int out_size)
{
    (void)in_sizes; (void)n_in; (void)out_size;
    const float* x     = (const float*)d_in[0];
    const float* eWih0 = (const float*)d_in[2];
    const float* eWhh0 = (const float*)d_in[3];
    const float* ebih0 = (const float*)d_in[4];
    const float* ebhh0 = (const float*)d_in[5];
    const float* eWih1 = (const float*)d_in[6];
    const float* eWhh1 = (const float*)d_in[7];
    const float* ebih1 = (const float*)d_in[8];
    const float* ebhh1 = (const float*)d_in[9];
    const float* dWih0 = (const float*)d_in[10];
    const float* dWhh0 = (const float*)d_in[11];
    const float* dbih0 = (const float*)d_in[12];
    const float* dbhh0 = (const float*)d_in[13];
    const float* dWih1 = (const float*)d_in[14];
    const float* dWhh1 = (const float*)d_in[15];
    const float* dbih1 = (const float*)d_in[16];
    const float* dbhh1 = (const float*)d_in[17];
    const float* dWlin = (const float*)d_in[18];
    const float* dblin = (const float*)d_in[19];
    float* out = (float*)d_out;

    // One-time side streams + events (resource setup only; identical GPU work
    // is issued on every call).
    static bool s_init = false;
    static cudaStream_t sA, sB;
    static cudaEvent_t eFork, eA[NCH], eAend, eBend;
    if (!s_init) {
        cudaStreamCreateWithFlags(&sA, cudaStreamNonBlocking);
        cudaStreamCreateWithFlags(&sB, cudaStreamNonBlocking);
        cudaEventCreateWithFlags(&eFork, cudaEventDisableTiming);
        for (int k = 0; k < NCH; ++k)
            cudaEventCreateWithFlags(&eA[k], cudaEventDisableTiming);
        cudaEventCreateWithFlags(&eAend, cudaEventDisableTiming);
        cudaEventCreateWithFlags(&eBend, cudaEventDisableTiming);
        s_init = true;
    }

    __half *ys0hi, *ys0lo, *h1hi, *h1lo, *hAhi, *hAlo, *hBhi, *hBlo, *zb, *Wd;
    float *Z1, *inp;
    cudaGetSymbolAddress((void**)&ys0hi, g_ys0_hi);
    cudaGetSymbolAddress((void**)&ys0lo, g_ys0_lo);
    cudaGetSymbolAddress((void**)&Z1,    g_Z1);
    cudaGetSymbolAddress((void**)&h1hi,  g_h1hi);
    cudaGetSymbolAddress((void**)&h1lo,  g_h1lo);
    cudaGetSymbolAddress((void**)&hAhi,  g_hAhi);
    cudaGetSymbolAddress((void**)&hAlo,  g_hAlo);
    cudaGetSymbolAddress((void**)&hBhi,  g_hBhi);
    cudaGetSymbolAddress((void**)&hBlo,  g_hBlo);
    cudaGetSymbolAddress((void**)&zb,    g_zb);
    cudaGetSymbolAddress((void**)&inp,   g_inp);
    cudaGetSymbolAddress((void**)&Wd,    g_W);

    const int HH = H_*H_;
    auto WF = [&](int i){ return Wd + (size_t)i*HH; };

    // ---- Setup on main stream ----
    k_init<<<(BH + 255)/256, 256>>>(x);
    const float* wsrc[6] = {eWhh0, eWih1, eWhh1, dWhh0, dWih1, dWhh1};
    for (int i = 0; i < 6; ++i)
        k_conv<<<HH/256, 256>>>(wsrc[i], WF(i), HH);
    cudaEventRecord(eFork, 0);
    cudaStreamWaitEvent(sA, eFork, 0);
    cudaStreamWaitEvent(sB, eFork, 0);

    const dim3 blk(128);
    const dim3 gstep(H_/BN, B_/BM);            // (16, 8) = 128 CTAs
    const dim3 gchunk(H_/BN, CH*B_/BM);        // (16, 256)

    // ---- Stream A: encoder layer 0 chain ----
    for (int t = 0; t < S_; ++t) {
        const __half* Ah = t ? (ys0hi + (size_t)(t-1)*BH) : zb;
        const __half* Al = t ? (ys0lo + (size_t)(t-1)*BH) : zb;
        k_mma<<<gstep, blk, 0, sA>>>(Ah, Al, WF(0),
                                     nullptr, nullptr, nullptr, 1,
                                     nullptr, x + t*I_, S_*I_, eWih0, ebih0, ebhh0,
                                     nullptr, ys0hi + (size_t)t*BH, ys0lo + (size_t)t*BH, 1);
        if ((t & (CH-1)) == CH-1)
            cudaEventRecord(eA[t/CH], sA);
    }
    cudaEventRecord(eAend, sA);

    // ---- Stream B: Z1 chunks + encoder layer 1 chain (lags A by one chunk) ----
    for (int k = 0; k < NCH; ++k) {
        cudaStreamWaitEvent(sB, eA[k], 0);
        // Z1[32k..32k+32) = ys0 @ eWih1^T + bih1 + bhh1   (fp32, no tanh)
        k_mma<<<gchunk, blk, 0, sB>>>(ys0hi + (size_t)k*CH*BH, ys0lo + (size_t)k*CH*BH, WF(1),
                                      nullptr, nullptr, nullptr, 1,
                                      nullptr, nullptr, 0, nullptr, ebih1, ebhh1,
                                      Z1 + (size_t)k*CH*BH, nullptr, nullptr, 0);
        for (int t = k*CH; t < (k+1)*CH; ++t) {
            const __half* Ah = t ? (h1hi + ((t-1)&1)*BH) : zb;
            const __half* Al = t ? (h1lo + ((t-1)&1)*BH) : zb;
            k_mma<<<gstep, blk, 0, sB>>>(Ah, Al, WF(2),
                                         nullptr, nullptr, nullptr, 1,
                                         Z1 + (size_t)t*BH, nullptr, 0, nullptr, nullptr, nullptr,
                                         nullptr, h1hi + (t&1)*BH, h1lo + (t&1)*BH, 1);
        }
    }
    cudaEventRecord(eBend, sB);

    // ---- Join, then decoder on main stream ----
    cudaStreamWaitEvent(0, eAend, 0);
    cudaStreamWaitEvent(0, eBend, 0);

    const __half* hAp_hi = ys0hi + (size_t)(S_-1)*BH;
    const __half* hAp_lo = ys0lo + (size_t)(S_-1)*BH;
    const __half* hBp_hi = h1hi + ((S_-1)&1)*BH;
    const __half* hBp_lo = h1lo + ((S_-1)&1)*BH;
    for (int t = 0; t < T_; ++t) {
        __half* hA_hi = hAhi + (t&1)*BH;
        __half* hA_lo = hAlo + (t&1)*BH;
        k_mma<<<gstep, blk>>>(hAp_hi, hAp_lo, WF(3),
                              nullptr, nullptr, nullptr, 1,
                              nullptr, inp, I_, dWih0, dbih0, dbhh0,
                              nullptr, hA_hi, hA_lo, 1);
        __half* hB_hi = hBhi + (t&1)*BH;
        __half* hB_lo = hBlo + (t&1)*BH;
        // hB = tanh(hA @ dWih1^T + hB_prev @ dWhh1^T + biases), K=2048 fused
        k_mma<<<gstep, blk>>>(hA_hi, hA_lo, WF(4),
                              hBp_hi, hBp_lo, WF(5), 2,
                              nullptr, nullptr, 0, nullptr, dbih1, dbhh1,
                              nullptr, hB_hi, hB_lo, 1);
        k_decout<<<32, 256>>>(hB_hi, hB_lo, dWlin, dblin, out, t);
        hAp_hi = hA_hi; hAp_lo = hA_lo;
        hBp_hi = hB_hi; hBp_lo = hB_lo;
    }
}